// round 14
// baseline (speedup 1.0000x reference)
#include <cuda_runtime.h>
#include <cuda_bf16.h>
#include <cstdint>

#define DINLINE __device__ __forceinline__

// ---------------- problem constants ----------------
static constexpr int BATCH = 8192;
static constexpr int J = 25;
static constexpr int FDIM = 512;
static constexpr int HDIM = 1024;
static constexpr long M_ROWS = (long)BATCH * J;   // 204800

// ---------------- scratch (device globals; no cudaMalloc allowed) ----------------
__device__ __nv_bfloat16 g_X[M_ROWS * FDIM];          // features bf16      [204800,512]
__device__ __nv_bfloat16 g_W1t[HDIM * FDIM];          // dW1^T bf16         [1024,512]
__device__ __nv_bfloat16 g_W2t[FDIM * HDIM];          // dW2^T bf16         [512,1024]
__device__ __nv_bfloat16 g_cW1T[32 * FDIM];           // cW1[4:]^T bf16     [32,512]
__device__ __nv_bfloat16 g_h1[M_ROWS * HDIM];         // relu(X@W1+b1)      [204800,1024]
__device__ float g_F1[M_ROWS * 32];                   // features@cW1f+cb1  [204800,32]
__device__ float g_depth[M_ROWS];                     // [204800]

__constant__ int c_PAR[16] = {0, 0, 0, 0, 0, 0, 5, 7, 6, 8, 5, 6, 11, 13, 12, 14};
__constant__ int c_CHI[16] = {1, 2, 3, 4, 5, 6, 7, 9, 8, 10, 11, 12, 13, 15, 14, 16};

// ---------------- PTX helpers (sm_80-level only; virtual arch is compute_103) ----------------
DINLINE uint32_t smem_u32(const void* p) {
    uint32_t a;
    asm("{ .reg .u64 t; cvta.to.shared.u64 t, %1; cvt.u32.u64 %0, t; }" : "=r"(a) : "l"(p));
    return a;
}
DINLINE uint32_t sw128(uint32_t off) { return off ^ ((off >> 3) & 0x70); }

DINLINE void cp_async16_cg(uint32_t dst, const void* src) {
    asm volatile(
        "{ .reg .u64 g; cvta.to.global.u64 g, %1; cp.async.cg.shared.global [%0], [g], 16; }"
        :: "r"(dst), "l"(src));
}
DINLINE void cp_async16_ca(uint32_t dst, const void* src) {
    asm volatile(
        "{ .reg .u64 g; cvta.to.global.u64 g, %1; cp.async.ca.shared.global [%0], [g], 16; }"
        :: "r"(dst), "l"(src));
}
#define CP_COMMIT() asm volatile("cp.async.commit_group;" ::: "memory")
template <int N>
DINLINE void cp_wait() { asm volatile("cp.async.wait_group %0;" :: "n"(N) : "memory"); }

DINLINE void ldsm_x4(uint32_t (&r)[4], uint32_t addr) {
    asm volatile("ldmatrix.sync.aligned.m8n8.x4.shared.b16 {%0,%1,%2,%3}, [%4];"
                 : "=r"(r[0]), "=r"(r[1]), "=r"(r[2]), "=r"(r[3]) : "r"(addr));
}

DINLINE void mma16816(float (&c)[4], const uint32_t (&a)[4], uint32_t b0, uint32_t b1) {
    asm volatile(
        "mma.sync.aligned.m16n8k16.row.col.f32.bf16.bf16.f32 "
        "{%0,%1,%2,%3},{%4,%5,%6,%7},{%8,%9},{%0,%1,%2,%3};"
        : "+f"(c[0]), "+f"(c[1]), "+f"(c[2]), "+f"(c[3])
        : "r"(a[0]), "r"(a[1]), "r"(a[2]), "r"(a[3]), "r"(b0), "r"(b1));
}

// ---------------- fused prep kernel (block-range partitioned) ----------------
__global__ __launch_bounds__(256) void prep_kernel(
    const float* __restrict__ feat, __nv_bfloat16* __restrict__ X,
    const float* __restrict__ dW1, __nv_bfloat16* __restrict__ W1t,
    const float* __restrict__ dW2, __nv_bfloat16* __restrict__ W2t,
    const float* __restrict__ cW1, __nv_bfloat16* __restrict__ cW1T,
    const float* __restrict__ db3, float* __restrict__ depth) {
    int b = blockIdx.x, tid = threadIdx.x;
    if (b < 2048) {
        long n4 = M_ROWS * FDIM / 4;
        for (long i = (long)b * 256 + tid; i < n4; i += 2048L * 256) {
            float4 v = reinterpret_cast<const float4*>(feat)[i];
            __nv_bfloat162 a = __floats2bfloat162_rn(v.x, v.y);
            __nv_bfloat162 c = __floats2bfloat162_rn(v.z, v.w);
            uint2 u;
            u.x = *reinterpret_cast<uint32_t*>(&a);
            u.y = *reinterpret_cast<uint32_t*>(&c);
            reinterpret_cast<uint2*>(X)[i] = u;
        }
    } else if (b < 2176) {
        int bb = b - 2048;
        for (int idx = bb * 256 + tid; idx < 512 * 1024; idx += 128 * 256) {
            int k = idx & 511, n = idx >> 9;
            W1t[idx] = __float2bfloat16(dW1[k * 1024 + n]);
        }
    } else if (b < 2304) {
        int bb = b - 2176;
        for (int idx = bb * 256 + tid; idx < 1024 * 512; idx += 128 * 256) {
            int k = idx & 1023, n = idx >> 10;
            W2t[idx] = __float2bfloat16(dW2[k * 512 + n]);
        }
    } else if (b < 2312) {
        int bb = b - 2304;
        const float* src = cW1 + 4 * 32;
        for (int idx = bb * 256 + tid; idx < 512 * 32; idx += 8 * 256) {
            int k = idx & 511, n = idx >> 9;
            cW1T[idx] = __float2bfloat16(src[k * 32 + n]);
        }
    } else {
        int bb = b - 2312;
        float v = db3[0];
        for (long i = (long)bb * 256 + tid; i < M_ROWS; i += 100L * 256) depth[i] = v;
    }
}

// ---------------- persistent HMMA GEMM: C = act(A[M,K] @ Bt[Ntot,K]^T + bias) ------
// BM=128, BK=64, NSTAGE cp.async pipeline, MINB CTAs/SM, persistent tile loop
// (grid = MINB*numSMs; removes tail-wave quantization + re-prologue cost).
// A loads: .cg (R12 showed .ca costs -24% tensor). B loads: .ca.
// OUTMODE: 0 = relu -> bf16 store, 1 = linear -> fp32 store,
//          2 = relu -> fused dot with w3 + atomicAdd into depth (no C store).
template <int THREADS, int BN, int WM, int WN, int OUTMODE, int NSTAGE, int MINB>
__global__ __launch_bounds__(THREADS, MINB)
void hgemm_kernel(const __nv_bfloat16* __restrict__ A, const __nv_bfloat16* __restrict__ Bt,
                  const float* __restrict__ bias, void* __restrict__ Cout,
                  const float* __restrict__ w3, int Ntot, int KTOT, int tilesX, int tilesTot) {
    constexpr int BM = 128;
    constexpr int NWARP = THREADS / 32;
    constexpr int WARPS_M = BM / WM, WARPS_N = BN / WN;
    static_assert(WARPS_M * WARPS_N == NWARP, "warp layout mismatch");
    constexpr int MF = WM / 16;
    constexpr int NT8 = WN / 8;
    constexpr int NG = WN / 16;
    constexpr int ST_A = BM * 128;
    constexpr int ST_B = BN * 128;
    constexpr int ST = ST_A + ST_B;
    constexpr int A_ITERS = BM * 8 / THREADS;
    constexpr int B_ITERS = BN * 8 / THREADS;

    extern __shared__ char smem[];
    __shared__ float sbias[BN];
    __shared__ float sw3[BN];
    uint32_t sb = smem_u32(smem);
    int tid = threadIdx.x, lane = tid & 31, wid = tid >> 5;
    int warpM = wid % WARPS_M, warpN = wid / WARPS_M;

    // tile-invariant precomputed offsets
    int aE[A_ITERS];
    uint32_t aD[A_ITERS];
#pragma unroll
    for (int i = 0; i < A_ITERS; i++) {
        int idx = tid + i * THREADS, row = idx >> 3, seg = idx & 7;
        aE[i] = row * KTOT + seg * 8;
        aD[i] = sw128((uint32_t)(row * 128 + seg * 16));
    }
    int bE[B_ITERS];
    uint32_t bD[B_ITERS];
#pragma unroll
    for (int i = 0; i < B_ITERS; i++) {
        int idx = tid + i * THREADS, row = idx >> 3, seg = idx & 7;
        bE[i] = row * KTOT + seg * 8;
        bD[i] = ST_A + sw128((uint32_t)(row * 128 + seg * 16));
    }
    uint32_t hi16 = (uint32_t)((lane >> 4) << 4);
    uint32_t aRow[MF], aXm[MF];
#pragma unroll
    for (int mf = 0; mf < MF; mf++) {
        int row = warpM * WM + mf * 16 + (lane & 15);
        aRow[mf] = (uint32_t)(row * 128);
        aXm[mf] = (uint32_t)((row & 7) << 4);
    }
    uint32_t bRow[NG], bXm[NG];
#pragma unroll
    for (int ng = 0; ng < NG; ng++) {
        int row = warpN * WN + ng * 16 + (lane & 15);
        bRow[ng] = (uint32_t)(ST_A + row * 128);
        bXm[ng] = (uint32_t)((row & 7) << 4);
    }
    int KT = KTOT / 64;

    for (int tile = blockIdx.x; tile < tilesTot; tile += gridDim.x) {
        int bx = tile % tilesX;
        long m0 = (long)(tile / tilesX) * BM;
        int n0 = bx * BN;

        __syncthreads();  // prior tile's epilogue reads of sbias/stage smem complete
        for (int i = tid; i < BN; i += THREADS) {
            sbias[i] = bias[n0 + i];
            if (OUTMODE == 2) sw3[i] = w3[n0 + i];
        }

        const __nv_bfloat16* Ag = A + m0 * KTOT;
        const __nv_bfloat16* Bg = Bt + (long)n0 * KTOT;

        auto load_stage = [&](int buf, int kt) {
            uint32_t base = sb + buf * ST;
            int ke = kt * 64;
#pragma unroll
            for (int i = 0; i < A_ITERS; i++) cp_async16_cg(base + aD[i], Ag + ke + aE[i]);
#pragma unroll
            for (int i = 0; i < B_ITERS; i++) cp_async16_ca(base + bD[i], Bg + ke + bE[i]);
            CP_COMMIT();
        };

        float acc[MF][NT8][4];
#pragma unroll
        for (int mf = 0; mf < MF; mf++)
#pragma unroll
            for (int nt = 0; nt < NT8; nt++)
#pragma unroll
                for (int q = 0; q < 4; q++) acc[mf][nt][q] = 0.f;

#pragma unroll
        for (int s = 0; s < NSTAGE - 1; s++) load_stage(s, s);

        for (int kt = 0; kt < KT; kt++) {
            int buf = kt % NSTAGE;
            cp_wait<NSTAGE - 2>();
            __syncthreads();
            if (kt + NSTAGE - 1 < KT) load_stage((kt + NSTAGE - 1) % NSTAGE, kt + NSTAGE - 1);
            else CP_COMMIT();  // keep group count uniform so wait_group guards stage kt

            uint32_t base = sb + buf * ST;
#pragma unroll
            for (int ks = 0; ks < 4; ks++) {
                uint32_t a[MF][4];
                uint32_t b[NT8][2];
                uint32_t kofs = ((uint32_t)(ks * 32)) | hi16;
#pragma unroll
                for (int mf = 0; mf < MF; mf++)
                    ldsm_x4(a[mf], base + aRow[mf] + (kofs ^ aXm[mf]));
#pragma unroll
                for (int ng = 0; ng < NG; ng++) {
                    uint32_t r[4];
                    ldsm_x4(r, base + bRow[ng] + (kofs ^ bXm[ng]));
                    b[2 * ng][0] = r[0]; b[2 * ng][1] = r[2];
                    b[2 * ng + 1][0] = r[1]; b[2 * ng + 1][1] = r[3];
                }
#pragma unroll
                for (int mf = 0; mf < MF; mf++)
#pragma unroll
                    for (int nt = 0; nt < NT8; nt++)
                        mma16816(acc[mf][nt], a[mf], b[nt][0], b[nt][1]);
            }
        }
        __syncthreads();

        // epilogue
#pragma unroll
        for (int mf = 0; mf < MF; mf++) {
            long r0 = m0 + warpM * WM + mf * 16 + (lane >> 2);
            float p0 = 0.f, p1 = 0.f;
#pragma unroll
            for (int nt = 0; nt < NT8; nt++) {
                int cb = warpN * WN + nt * 8 + (lane & 3) * 2;
                float v0 = acc[mf][nt][0] + sbias[cb];
                float v1 = acc[mf][nt][1] + sbias[cb + 1];
                float v2 = acc[mf][nt][2] + sbias[cb];
                float v3 = acc[mf][nt][3] + sbias[cb + 1];
                if (OUTMODE != 1) {
                    v0 = fmaxf(v0, 0.f); v1 = fmaxf(v1, 0.f);
                    v2 = fmaxf(v2, 0.f); v3 = fmaxf(v3, 0.f);
                }
                if (OUTMODE == 0) {
                    __nv_bfloat16* out = reinterpret_cast<__nv_bfloat16*>(Cout);
                    __nv_bfloat162 h0 = __floats2bfloat162_rn(v0, v1);
                    __nv_bfloat162 h1 = __floats2bfloat162_rn(v2, v3);
                    *reinterpret_cast<uint32_t*>(out + r0 * Ntot + n0 + cb) =
                        *reinterpret_cast<uint32_t*>(&h0);
                    *reinterpret_cast<uint32_t*>(out + (r0 + 8) * Ntot + n0 + cb) =
                        *reinterpret_cast<uint32_t*>(&h1);
                } else if (OUTMODE == 1) {
                    float* out = reinterpret_cast<float*>(Cout);
                    *reinterpret_cast<float2*>(out + r0 * Ntot + n0 + cb) = make_float2(v0, v1);
                    *reinterpret_cast<float2*>(out + (r0 + 8) * Ntot + n0 + cb) =
                        make_float2(v2, v3);
                } else {
                    float w0 = sw3[cb], w1 = sw3[cb + 1];
                    p0 = fmaf(v0, w0, fmaf(v1, w1, p0));
                    p1 = fmaf(v2, w0, fmaf(v3, w1, p1));
                }
            }
            if (OUTMODE == 2) {
                p0 += __shfl_xor_sync(0xffffffffu, p0, 1);
                p0 += __shfl_xor_sync(0xffffffffu, p0, 2);
                p1 += __shfl_xor_sync(0xffffffffu, p1, 1);
                p1 += __shfl_xor_sync(0xffffffffu, p1, 2);
                if ((lane & 3) == 0) {
                    float* depth = reinterpret_cast<float*>(Cout);
                    atomicAdd(depth + r0, p0);
                    atomicAdd(depth + r0 + 8, p1);
                }
            }
        }
    }
}

// ---------------- bone refinement: NB bodies per block, 1 warp per bone ----------------
static constexpr int NB = 16;  // bodies per block
__global__ __launch_bounds__(512) void bones_kernel(
    const float* __restrict__ poses2d, const float* __restrict__ confid,
    const float* __restrict__ depth, const float* __restrict__ F1,
    const float* __restrict__ cW1, const float* __restrict__ cW2,
    const float* __restrict__ cb2, const float* __restrict__ cW3,
    const float* __restrict__ cb3, float* __restrict__ out) {
    extern __shared__ float sm[];
    float* sp = sm;                 // NB*75
    float* sc = sp + NB * 75;       // NB*25
    float* sbf = sc + NB * 25;      // NB*48
    float* supd = sbf + NB * 48;    // NB*3
    float* sW2 = supd + NB * 3;     // 2048
    float* spre = sW2 + 2048;       // 16*NB*32

    int tid = threadIdx.x, wid = tid >> 5, lane = tid & 31;
    long base = (long)blockIdx.x * NB;

    for (int i = tid; i < 2048; i += 512) sW2[i] = cW2[i];
    for (int idx = tid; idx < NB * 25; idx += 512) {
        long row = base * 25 + idx;
        sc[idx] = confid[row];
        sp[idx * 3 + 0] = poses2d[row * 2 + 0];
        sp[idx * 3 + 1] = poses2d[row * 2 + 1];
        sp[idx * 3 + 2] = depth[row];
    }
    int e = wid;
    int pj = c_PAR[e], cj = c_CHI[e];
    for (int b = 0; b < NB; b++) {
        spre[(e * NB + b) * 32 + lane] =
            0.5f * (F1[((base + b) * 25 + pj) * 32 + lane] +
                    F1[((base + b) * 25 + cj) * 32 + lane]);
    }
    float w1k0 = cW1[0 * 32 + lane], w1k1 = cW1[1 * 32 + lane];
    float w1k2 = cW1[2 * 32 + lane], w1k3 = cW1[3 * 32 + lane];
    float w30 = cW3[(2 * lane) * 3 + 0], w31 = cW3[(2 * lane) * 3 + 1], w32 = cW3[(2 * lane) * 3 + 2];
    float w33 = cW3[(2 * lane + 1) * 3 + 0], w34 = cW3[(2 * lane + 1) * 3 + 1], w35 = cW3[(2 * lane + 1) * 3 + 2];
    float c2a = cb2[2 * lane], c2b = cb2[2 * lane + 1];
    __syncthreads();

    float w2a[32], w2b[32];
#pragma unroll
    for (int i = 0; i < 32; i++) {
        w2a[i] = sW2[i * 64 + 2 * lane];
        w2b[i] = sW2[i * 64 + 2 * lane + 1];
    }

    for (int it = 0; it < 3; it++) {
        for (int b = 0; b < NB; b++) {
            const float* spb = sp + b * 75;
            float vx = spb[cj * 3 + 0] - spb[pj * 3 + 0];
            float vy = spb[cj * 3 + 1] - spb[pj * 3 + 1];
            float vz = spb[cj * 3 + 2] - spb[pj * 3 + 2];
            float len = sqrtf(vx * vx + vy * vy + vz * vz);
            float inv = 1.0f / (len + 1e-8f);
            float pre = spre[(e * NB + b) * 32 + lane];
            float g1 = fmaxf(pre + vx * inv * w1k0 + vy * inv * w1k1 + vz * inv * w1k2 + len * w1k3, 0.f);
            float a0 = c2a, a1 = c2b;
#pragma unroll
            for (int i = 0; i < 32; i++) {
                float g = __shfl_sync(0xffffffffu, g1, i);
                a0 = fmaf(g, w2a[i], a0);
                a1 = fmaf(g, w2b[i], a1);
            }
            a0 = fmaxf(a0, 0.f);
            a1 = fmaxf(a1, 0.f);
            float f0 = a0 * w30 + a1 * w33;
            float f1 = a0 * w31 + a1 * w34;
            float f2 = a0 * w32 + a1 * w35;
#pragma unroll
            for (int o = 16; o; o >>= 1) {
                f0 += __shfl_xor_sync(0xffffffffu, f0, o);
                f1 += __shfl_xor_sync(0xffffffffu, f1, o);
                f2 += __shfl_xor_sync(0xffffffffu, f2, o);
            }
            if (lane == 0) {
                sbf[b * 48 + e * 3 + 0] = f0;
                sbf[b * 48 + e * 3 + 1] = f1;
                sbf[b * 48 + e * 3 + 2] = f2;
            }
        }
        __syncthreads();
        if (tid < NB * 3) {
            int body = tid / 3, k = tid % 3;
            float s = 0.f;
            for (int q = 0; q < 16; q++) s += sbf[body * 48 + q * 3 + k];
            supd[tid] = cb3[k] + s * (1.0f / 16.0f);
        }
        __syncthreads();
        for (int idx = tid; idx < NB * 75; idx += 512) {
            int body = idx / 75, r = idx % 75, j = r / 3, k = r % 3;
            sp[idx] = (sp[idx] + 0.1f * supd[body * 3 + k]) * sc[body * 25 + j];
        }
        __syncthreads();
    }
    for (int idx = tid; idx < NB * 75; idx += 512) out[base * 75 + idx] = sp[idx];
}

// ---------------- launcher ----------------
extern "C" void kernel_launch(void* const* d_in, const int* in_sizes, int n_in,
                              void* d_out, int out_size) {
    const float* poses2d = (const float*)d_in[0];
    const float* features = (const float*)d_in[1];
    const float* confid = (const float*)d_in[2];
    const float* dW1 = (const float*)d_in[3];
    const float* db1 = (const float*)d_in[4];
    const float* dW2 = (const float*)d_in[5];
    const float* db2 = (const float*)d_in[6];
    const float* dW3 = (const float*)d_in[7];
    const float* db3 = (const float*)d_in[8];
    const float* cW1 = (const float*)d_in[9];
    const float* cb1 = (const float*)d_in[10];
    const float* cW2 = (const float*)d_in[11];
    const float* cb2 = (const float*)d_in[12];
    const float* cW3 = (const float*)d_in[13];
    const float* cb3 = (const float*)d_in[14];
    float* out = (float*)d_out;

    __nv_bfloat16 *X, *W1t, *W2t, *cW1T, *h1;
    float *F1, *dep;
    cudaGetSymbolAddress((void**)&X, g_X);
    cudaGetSymbolAddress((void**)&W1t, g_W1t);
    cudaGetSymbolAddress((void**)&W2t, g_W2t);
    cudaGetSymbolAddress((void**)&cW1T, g_cW1T);
    cudaGetSymbolAddress((void**)&h1, g_h1);
    cudaGetSymbolAddress((void**)&F1, g_F1);
    cudaGetSymbolAddress((void**)&dep, g_depth);

    int numSMs = 148;
    cudaDeviceGetAttribute(&numSMs, cudaDevAttrMultiProcessorCount, 0);

    // launch 0: fused prep (cvt + transposes + depth init)
    prep_kernel<<<2412, 256>>>(features, X, dW1, W1t, dW2, W2t, cW1, cW1T, db3, dep);

    constexpr int SMEM_BN128 = 2 * (128 * 128 + 128 * 128);  // 65536, MINB=3
    constexpr int SMEM_F1 = 2 * (128 * 128 + 32 * 128);      // 40960, MINB=4
    constexpr int SMEM_BONES = (NB * 75 + NB * 25 + NB * 48 + NB * 3 + 2048 + 16 * NB * 32) * 4;

    cudaFuncSetAttribute(hgemm_kernel<128, 128, 64, 64, 0, 2, 3>,
                         cudaFuncAttributeMaxDynamicSharedMemorySize, SMEM_BN128);
    cudaFuncSetAttribute(hgemm_kernel<128, 128, 64, 64, 2, 2, 3>,
                         cudaFuncAttributeMaxDynamicSharedMemorySize, SMEM_BN128);
    cudaFuncSetAttribute(hgemm_kernel<128, 32, 32, 32, 1, 2, 4>,
                         cudaFuncAttributeMaxDynamicSharedMemorySize, SMEM_F1);
    cudaFuncSetAttribute(bones_kernel,
                         cudaFuncAttributeMaxDynamicSharedMemorySize, SMEM_BONES);

    const int MT = (int)(M_ROWS / 128);  // 1600 row tiles
    int gridBig = 3 * numSMs;            // persistent, MINB=3
    int gridF1 = 4 * numSMs;             // persistent, MINB=4

    // launch 1: F1 = X @ cW1[4:] + cb1 (fp32 out)
    hgemm_kernel<128, 32, 32, 32, 1, 2, 4>
        <<<gridF1 < MT ? gridF1 : MT, 128, SMEM_F1>>>(X, cW1T, cb1, (void*)F1, nullptr,
                                                      32, FDIM, 1, MT);
    // launch 2: h1 = relu(X @ dW1 + db1)  (8 x 1600 tiles)
    hgemm_kernel<128, 128, 64, 64, 0, 2, 3>
        <<<gridBig, 128, SMEM_BN128>>>(X, W1t, db1, (void*)h1, nullptr,
                                       HDIM, FDIM, 8, 8 * MT);
    // launch 3: depth += relu(h1 @ dW2 + db2) @ dW3  (4 x 1600 tiles)
    hgemm_kernel<128, 128, 64, 64, 2, 2, 3>
        <<<gridBig, 128, SMEM_BN128>>>(h1, W2t, db2, (void*)dep, dW3,
                                       HDIM / 2, HDIM, 4, 4 * MT);
    // launch 4: bone refinement (NB bodies per block)
    bones_kernel<<<BATCH / NB, 512, SMEM_BONES>>>(poses2d, confid, dep, F1, cW1, cW2, cb2, cW3,
                                                  cb3, out);
}

// round 15
// speedup vs baseline: 1.0998x; 1.0998x over previous
#include <cuda_runtime.h>
#include <cuda_bf16.h>
#include <cstdint>

#define DINLINE __device__ __forceinline__

// ---------------- problem constants ----------------
static constexpr int BATCH = 8192;
static constexpr int J = 25;
static constexpr int FDIM = 512;
static constexpr int HDIM = 1024;
static constexpr long M_ROWS = (long)BATCH * J;   // 204800

// ---------------- scratch (device globals; no cudaMalloc allowed) ----------------
__device__ __nv_bfloat16 g_X[M_ROWS * FDIM];          // features bf16      [204800,512]
__device__ __nv_bfloat16 g_W1t[HDIM * FDIM];          // dW1^T bf16         [1024,512]
__device__ __nv_bfloat16 g_W2t[FDIM * HDIM];          // dW2^T bf16         [512,1024]
__device__ __nv_bfloat16 g_cW1T[32 * FDIM];           // cW1[4:]^T bf16     [32,512]
__device__ __nv_bfloat16 g_h1[M_ROWS * HDIM];         // relu(X@W1+b1)      [204800,1024]
__device__ float g_F1[M_ROWS * 32];                   // features@cW1f+cb1  [204800,32]
__device__ float g_depth[M_ROWS];                     // [204800]

__constant__ int c_PAR[16] = {0, 0, 0, 0, 0, 0, 5, 7, 6, 8, 5, 6, 11, 13, 12, 14};
__constant__ int c_CHI[16] = {1, 2, 3, 4, 5, 6, 7, 9, 8, 10, 11, 12, 13, 15, 14, 16};

// ---------------- PTX helpers (sm_80-level only; virtual arch is compute_103) ----------------
DINLINE uint32_t smem_u32(const void* p) {
    uint32_t a;
    asm("{ .reg .u64 t; cvta.to.shared.u64 t, %1; cvt.u32.u64 %0, t; }" : "=r"(a) : "l"(p));
    return a;
}
DINLINE uint32_t sw128(uint32_t off) { return off ^ ((off >> 3) & 0x70); }

DINLINE void cp_async16_cg(uint32_t dst, const void* src) {
    asm volatile(
        "{ .reg .u64 g; cvta.to.global.u64 g, %1; cp.async.cg.shared.global [%0], [g], 16; }"
        :: "r"(dst), "l"(src));
}
DINLINE void cp_async16_ca(uint32_t dst, const void* src) {
    asm volatile(
        "{ .reg .u64 g; cvta.to.global.u64 g, %1; cp.async.ca.shared.global [%0], [g], 16; }"
        :: "r"(dst), "l"(src));
}
#define CP_COMMIT() asm volatile("cp.async.commit_group;" ::: "memory")
template <int N>
DINLINE void cp_wait() { asm volatile("cp.async.wait_group %0;" :: "n"(N) : "memory"); }

DINLINE void ldsm_x4(uint32_t (&r)[4], uint32_t addr) {
    asm volatile("ldmatrix.sync.aligned.m8n8.x4.shared.b16 {%0,%1,%2,%3}, [%4];"
                 : "=r"(r[0]), "=r"(r[1]), "=r"(r[2]), "=r"(r[3]) : "r"(addr));
}

DINLINE void mma16816(float (&c)[4], const uint32_t (&a)[4], uint32_t b0, uint32_t b1) {
    asm volatile(
        "mma.sync.aligned.m16n8k16.row.col.f32.bf16.bf16.f32 "
        "{%0,%1,%2,%3},{%4,%5,%6,%7},{%8,%9},{%0,%1,%2,%3};"
        : "+f"(c[0]), "+f"(c[1]), "+f"(c[2]), "+f"(c[3])
        : "r"(a[0]), "r"(a[1]), "r"(a[2]), "r"(a[3]), "r"(b0), "r"(b1));
}

// ---------------- fused prep kernel (block-range partitioned) ----------------
__global__ __launch_bounds__(256) void prep_kernel(
    const float* __restrict__ feat, __nv_bfloat16* __restrict__ X,
    const float* __restrict__ dW1, __nv_bfloat16* __restrict__ W1t,
    const float* __restrict__ dW2, __nv_bfloat16* __restrict__ W2t,
    const float* __restrict__ cW1, __nv_bfloat16* __restrict__ cW1T,
    const float* __restrict__ db3, float* __restrict__ depth) {
    int b = blockIdx.x, tid = threadIdx.x;
    if (b < 2048) {
        long n4 = M_ROWS * FDIM / 4;
        for (long i = (long)b * 256 + tid; i < n4; i += 2048L * 256) {
            float4 v = reinterpret_cast<const float4*>(feat)[i];
            __nv_bfloat162 a = __floats2bfloat162_rn(v.x, v.y);
            __nv_bfloat162 c = __floats2bfloat162_rn(v.z, v.w);
            uint2 u;
            u.x = *reinterpret_cast<uint32_t*>(&a);
            u.y = *reinterpret_cast<uint32_t*>(&c);
            reinterpret_cast<uint2*>(X)[i] = u;
        }
    } else if (b < 2176) {
        int bb = b - 2048;
        for (int idx = bb * 256 + tid; idx < 512 * 1024; idx += 128 * 256) {
            int k = idx & 511, n = idx >> 9;
            W1t[idx] = __float2bfloat16(dW1[k * 1024 + n]);
        }
    } else if (b < 2304) {
        int bb = b - 2176;
        for (int idx = bb * 256 + tid; idx < 1024 * 512; idx += 128 * 256) {
            int k = idx & 1023, n = idx >> 10;
            W2t[idx] = __float2bfloat16(dW2[k * 512 + n]);
        }
    } else if (b < 2312) {
        int bb = b - 2304;
        const float* src = cW1 + 4 * 32;
        for (int idx = bb * 256 + tid; idx < 512 * 32; idx += 8 * 256) {
            int k = idx & 511, n = idx >> 9;
            cW1T[idx] = __float2bfloat16(src[k * 32 + n]);
        }
    } else {
        int bb = b - 2312;
        float v = db3[0];
        for (long i = (long)bb * 256 + tid; i < M_ROWS; i += 100L * 256) depth[i] = v;
    }
}

// ---------------- HMMA GEMM: C = act(A[M,K] @ Bt[Ntot,K]^T + bias) ----------------
// R13 configuration (best measured, reproduced 3x). BM=128, BK=64, NSTAGE
// cp.async pipeline, MINB CTAs/SM. A loads .cg, B loads .ca.
// OUTMODE: 0 = relu -> bf16 store, 1 = linear -> fp32 store,
//          2 = relu -> fused dot with w3 + atomicAdd into depth (no C store).
template <int THREADS, int BN, int WM, int WN, int OUTMODE, int NSTAGE, int MINB>
__global__ __launch_bounds__(THREADS, MINB)
void hgemm_kernel(const __nv_bfloat16* __restrict__ A, const __nv_bfloat16* __restrict__ Bt,
                  const float* __restrict__ bias, void* __restrict__ Cout,
                  const float* __restrict__ w3, int Ntot, int KTOT) {
    constexpr int BM = 128;
    constexpr int NWARP = THREADS / 32;
    constexpr int WARPS_M = BM / WM, WARPS_N = BN / WN;
    static_assert(WARPS_M * WARPS_N == NWARP, "warp layout mismatch");
    constexpr int MF = WM / 16;
    constexpr int NT8 = WN / 8;
    constexpr int NG = WN / 16;
    constexpr int ST_A = BM * 128;
    constexpr int ST_B = BN * 128;
    constexpr int ST = ST_A + ST_B;
    constexpr int A_ITERS = BM * 8 / THREADS;
    constexpr int B_ITERS = BN * 8 / THREADS;

    extern __shared__ char smem[];
    __shared__ float sbias[BN];
    __shared__ float sw3[BN];
    uint32_t sb = smem_u32(smem);
    int tid = threadIdx.x, lane = tid & 31, wid = tid >> 5;
    int warpM = wid % WARPS_M, warpN = wid / WARPS_M;
    long m0 = (long)blockIdx.y * BM;
    int n0 = blockIdx.x * BN;

    for (int i = tid; i < BN; i += THREADS) {
        sbias[i] = bias[n0 + i];
        if (OUTMODE == 2) sw3[i] = w3[n0 + i];
    }

    const __nv_bfloat16* Ag = A + m0 * KTOT;
    const __nv_bfloat16* Bg = Bt + (long)n0 * KTOT;

    int aE[A_ITERS];
    uint32_t aD[A_ITERS];
#pragma unroll
    for (int i = 0; i < A_ITERS; i++) {
        int idx = tid + i * THREADS, row = idx >> 3, seg = idx & 7;
        aE[i] = row * KTOT + seg * 8;
        aD[i] = sw128((uint32_t)(row * 128 + seg * 16));
    }
    int bE[B_ITERS];
    uint32_t bD[B_ITERS];
#pragma unroll
    for (int i = 0; i < B_ITERS; i++) {
        int idx = tid + i * THREADS, row = idx >> 3, seg = idx & 7;
        bE[i] = row * KTOT + seg * 8;
        bD[i] = ST_A + sw128((uint32_t)(row * 128 + seg * 16));
    }

    auto load_stage = [&](int buf, int kt) {
        uint32_t base = sb + buf * ST;
        int ke = kt * 64;
#pragma unroll
        for (int i = 0; i < A_ITERS; i++) cp_async16_cg(base + aD[i], Ag + ke + aE[i]);
#pragma unroll
        for (int i = 0; i < B_ITERS; i++) cp_async16_ca(base + bD[i], Bg + ke + bE[i]);
        CP_COMMIT();
    };

    uint32_t hi16 = (uint32_t)((lane >> 4) << 4);
    uint32_t aRow[MF], aXm[MF];
#pragma unroll
    for (int mf = 0; mf < MF; mf++) {
        int row = warpM * WM + mf * 16 + (lane & 15);
        aRow[mf] = (uint32_t)(row * 128);
        aXm[mf] = (uint32_t)((row & 7) << 4);
    }
    uint32_t bRow[NG], bXm[NG];
#pragma unroll
    for (int ng = 0; ng < NG; ng++) {
        int row = warpN * WN + ng * 16 + (lane & 15);
        bRow[ng] = (uint32_t)(ST_A + row * 128);
        bXm[ng] = (uint32_t)((row & 7) << 4);
    }

    float acc[MF][NT8][4];
#pragma unroll
    for (int mf = 0; mf < MF; mf++)
#pragma unroll
        for (int nt = 0; nt < NT8; nt++)
#pragma unroll
            for (int q = 0; q < 4; q++) acc[mf][nt][q] = 0.f;

    int KT = KTOT / 64;
#pragma unroll
    for (int s = 0; s < NSTAGE - 1; s++) load_stage(s, s);

    for (int kt = 0; kt < KT; kt++) {
        int buf = kt % NSTAGE;
        cp_wait<NSTAGE - 2>();
        __syncthreads();
        if (kt + NSTAGE - 1 < KT) load_stage((kt + NSTAGE - 1) % NSTAGE, kt + NSTAGE - 1);
        else CP_COMMIT();  // keep group count uniform so wait_group guards stage kt

        uint32_t base = sb + buf * ST;
#pragma unroll
        for (int ks = 0; ks < 4; ks++) {
            uint32_t a[MF][4];
            uint32_t b[NT8][2];
            uint32_t kofs = ((uint32_t)(ks * 32)) | hi16;
#pragma unroll
            for (int mf = 0; mf < MF; mf++)
                ldsm_x4(a[mf], base + aRow[mf] + (kofs ^ aXm[mf]));
#pragma unroll
            for (int ng = 0; ng < NG; ng++) {
                uint32_t r[4];
                ldsm_x4(r, base + bRow[ng] + (kofs ^ bXm[ng]));
                b[2 * ng][0] = r[0]; b[2 * ng][1] = r[2];
                b[2 * ng + 1][0] = r[1]; b[2 * ng + 1][1] = r[3];
            }
#pragma unroll
            for (int mf = 0; mf < MF; mf++)
#pragma unroll
                for (int nt = 0; nt < NT8; nt++)
                    mma16816(acc[mf][nt], a[mf], b[nt][0], b[nt][1]);
        }
    }
    __syncthreads();

    // epilogue
#pragma unroll
    for (int mf = 0; mf < MF; mf++) {
        long r0 = m0 + warpM * WM + mf * 16 + (lane >> 2);
        float p0 = 0.f, p1 = 0.f;
#pragma unroll
        for (int nt = 0; nt < NT8; nt++) {
            int cb = warpN * WN + nt * 8 + (lane & 3) * 2;
            float v0 = acc[mf][nt][0] + sbias[cb];
            float v1 = acc[mf][nt][1] + sbias[cb + 1];
            float v2 = acc[mf][nt][2] + sbias[cb];
            float v3 = acc[mf][nt][3] + sbias[cb + 1];
            if (OUTMODE != 1) {
                v0 = fmaxf(v0, 0.f); v1 = fmaxf(v1, 0.f);
                v2 = fmaxf(v2, 0.f); v3 = fmaxf(v3, 0.f);
            }
            if (OUTMODE == 0) {
                __nv_bfloat16* out = reinterpret_cast<__nv_bfloat16*>(Cout);
                __nv_bfloat162 h0 = __floats2bfloat162_rn(v0, v1);
                __nv_bfloat162 h1 = __floats2bfloat162_rn(v2, v3);
                *reinterpret_cast<uint32_t*>(out + r0 * Ntot + n0 + cb) =
                    *reinterpret_cast<uint32_t*>(&h0);
                *reinterpret_cast<uint32_t*>(out + (r0 + 8) * Ntot + n0 + cb) =
                    *reinterpret_cast<uint32_t*>(&h1);
            } else if (OUTMODE == 1) {
                float* out = reinterpret_cast<float*>(Cout);
                *reinterpret_cast<float2*>(out + r0 * Ntot + n0 + cb) = make_float2(v0, v1);
                *reinterpret_cast<float2*>(out + (r0 + 8) * Ntot + n0 + cb) = make_float2(v2, v3);
            } else {
                float w0 = sw3[cb], w1 = sw3[cb + 1];
                p0 = fmaf(v0, w0, fmaf(v1, w1, p0));
                p1 = fmaf(v2, w0, fmaf(v3, w1, p1));
            }
        }
        if (OUTMODE == 2) {
            p0 += __shfl_xor_sync(0xffffffffu, p0, 1);
            p0 += __shfl_xor_sync(0xffffffffu, p0, 2);
            p1 += __shfl_xor_sync(0xffffffffu, p1, 1);
            p1 += __shfl_xor_sync(0xffffffffu, p1, 2);
            if ((lane & 3) == 0) {
                float* depth = reinterpret_cast<float*>(Cout);
                atomicAdd(depth + r0, p0);
                atomicAdd(depth + r0 + 8, p1);
            }
        }
    }
}

// ---------------- bone refinement: NB bodies per block, 1 warp per bone ----------------
static constexpr int NB = 16;  // bodies per block
__global__ __launch_bounds__(512) void bones_kernel(
    const float* __restrict__ poses2d, const float* __restrict__ confid,
    const float* __restrict__ depth, const float* __restrict__ F1,
    const float* __restrict__ cW1, const float* __restrict__ cW2,
    const float* __restrict__ cb2, const float* __restrict__ cW3,
    const float* __restrict__ cb3, float* __restrict__ out) {
    extern __shared__ float sm[];
    float* sp = sm;                 // NB*75
    float* sc = sp + NB * 75;       // NB*25
    float* sbf = sc + NB * 25;      // NB*48
    float* supd = sbf + NB * 48;    // NB*3
    float* sW2 = supd + NB * 3;     // 2048
    float* spre = sW2 + 2048;       // 16*NB*32

    int tid = threadIdx.x, wid = tid >> 5, lane = tid & 31;
    long base = (long)blockIdx.x * NB;

    for (int i = tid; i < 2048; i += 512) sW2[i] = cW2[i];
    for (int idx = tid; idx < NB * 25; idx += 512) {
        long row = base * 25 + idx;
        sc[idx] = confid[row];
        sp[idx * 3 + 0] = poses2d[row * 2 + 0];
        sp[idx * 3 + 1] = poses2d[row * 2 + 1];
        sp[idx * 3 + 2] = depth[row];
    }
    int e = wid;
    int pj = c_PAR[e], cj = c_CHI[e];
    for (int b = 0; b < NB; b++) {
        spre[(e * NB + b) * 32 + lane] =
            0.5f * (F1[((base + b) * 25 + pj) * 32 + lane] +
                    F1[((base + b) * 25 + cj) * 32 + lane]);
    }
    float w1k0 = cW1[0 * 32 + lane], w1k1 = cW1[1 * 32 + lane];
    float w1k2 = cW1[2 * 32 + lane], w1k3 = cW1[3 * 32 + lane];
    float w30 = cW3[(2 * lane) * 3 + 0], w31 = cW3[(2 * lane) * 3 + 1], w32 = cW3[(2 * lane) * 3 + 2];
    float w33 = cW3[(2 * lane + 1) * 3 + 0], w34 = cW3[(2 * lane + 1) * 3 + 1], w35 = cW3[(2 * lane + 1) * 3 + 2];
    float c2a = cb2[2 * lane], c2b = cb2[2 * lane + 1];
    __syncthreads();

    float w2a[32], w2b[32];
#pragma unroll
    for (int i = 0; i < 32; i++) {
        w2a[i] = sW2[i * 64 + 2 * lane];
        w2b[i] = sW2[i * 64 + 2 * lane + 1];
    }

    for (int it = 0; it < 3; it++) {
        for (int b = 0; b < NB; b++) {
            const float* spb = sp + b * 75;
            float vx = spb[cj * 3 + 0] - spb[pj * 3 + 0];
            float vy = spb[cj * 3 + 1] - spb[pj * 3 + 1];
            float vz = spb[cj * 3 + 2] - spb[pj * 3 + 2];
            float len = sqrtf(vx * vx + vy * vy + vz * vz);
            float inv = 1.0f / (len + 1e-8f);
            float pre = spre[(e * NB + b) * 32 + lane];
            float g1 = fmaxf(pre + vx * inv * w1k0 + vy * inv * w1k1 + vz * inv * w1k2 + len * w1k3, 0.f);
            float a0 = c2a, a1 = c2b;
#pragma unroll
            for (int i = 0; i < 32; i++) {
                float g = __shfl_sync(0xffffffffu, g1, i);
                a0 = fmaf(g, w2a[i], a0);
                a1 = fmaf(g, w2b[i], a1);
            }
            a0 = fmaxf(a0, 0.f);
            a1 = fmaxf(a1, 0.f);
            float f0 = a0 * w30 + a1 * w33;
            float f1 = a0 * w31 + a1 * w34;
            float f2 = a0 * w32 + a1 * w35;
#pragma unroll
            for (int o = 16; o; o >>= 1) {
                f0 += __shfl_xor_sync(0xffffffffu, f0, o);
                f1 += __shfl_xor_sync(0xffffffffu, f1, o);
                f2 += __shfl_xor_sync(0xffffffffu, f2, o);
            }
            if (lane == 0) {
                sbf[b * 48 + e * 3 + 0] = f0;
                sbf[b * 48 + e * 3 + 1] = f1;
                sbf[b * 48 + e * 3 + 2] = f2;
            }
        }
        __syncthreads();
        if (tid < NB * 3) {
            int body = tid / 3, k = tid % 3;
            float s = 0.f;
            for (int q = 0; q < 16; q++) s += sbf[body * 48 + q * 3 + k];
            supd[tid] = cb3[k] + s * (1.0f / 16.0f);
        }
        __syncthreads();
        for (int idx = tid; idx < NB * 75; idx += 512) {
            int body = idx / 75, r = idx % 75, j = r / 3, k = r % 3;
            sp[idx] = (sp[idx] + 0.1f * supd[body * 3 + k]) * sc[body * 25 + j];
        }
        __syncthreads();
    }
    for (int idx = tid; idx < NB * 75; idx += 512) out[base * 75 + idx] = sp[idx];
}

// ---------------- launcher ----------------
extern "C" void kernel_launch(void* const* d_in, const int* in_sizes, int n_in,
                              void* d_out, int out_size) {
    const float* poses2d = (const float*)d_in[0];
    const float* features = (const float*)d_in[1];
    const float* confid = (const float*)d_in[2];
    const float* dW1 = (const float*)d_in[3];
    const float* db1 = (const float*)d_in[4];
    const float* dW2 = (const float*)d_in[5];
    const float* db2 = (const float*)d_in[6];
    const float* dW3 = (const float*)d_in[7];
    const float* db3 = (const float*)d_in[8];
    const float* cW1 = (const float*)d_in[9];
    const float* cb1 = (const float*)d_in[10];
    const float* cW2 = (const float*)d_in[11];
    const float* cb2 = (const float*)d_in[12];
    const float* cW3 = (const float*)d_in[13];
    const float* cb3 = (const float*)d_in[14];
    float* out = (float*)d_out;

    __nv_bfloat16 *X, *W1t, *W2t, *cW1T, *h1;
    float *F1, *dep;
    cudaGetSymbolAddress((void**)&X, g_X);
    cudaGetSymbolAddress((void**)&W1t, g_W1t);
    cudaGetSymbolAddress((void**)&W2t, g_W2t);
    cudaGetSymbolAddress((void**)&cW1T, g_cW1T);
    cudaGetSymbolAddress((void**)&h1, g_h1);
    cudaGetSymbolAddress((void**)&F1, g_F1);
    cudaGetSymbolAddress((void**)&dep, g_depth);

    // lazy-created side stream + events (handles reused every call; created on the
    // eager correctness call, before graph capture begins — no work differences)
    static cudaStream_t s2 = nullptr;
    static cudaEvent_t evPrep = nullptr, evF1 = nullptr;
    if (!s2) {
        cudaStreamCreateWithFlags(&s2, cudaStreamNonBlocking);
        cudaEventCreateWithFlags(&evPrep, cudaEventDisableTiming);
        cudaEventCreateWithFlags(&evF1, cudaEventDisableTiming);
    }

    constexpr int SMEM_BN128 = 2 * (128 * 128 + 128 * 128);  // 65536, MINB=3
    constexpr int SMEM_F1 = 2 * (128 * 128 + 32 * 128);      // 40960, MINB=4
    constexpr int SMEM_BONES = (NB * 75 + NB * 25 + NB * 48 + NB * 3 + 2048 + 16 * NB * 32) * 4;

    cudaFuncSetAttribute(hgemm_kernel<128, 128, 64, 64, 0, 2, 3>,
                         cudaFuncAttributeMaxDynamicSharedMemorySize, SMEM_BN128);
    cudaFuncSetAttribute(hgemm_kernel<128, 128, 64, 64, 2, 2, 3>,
                         cudaFuncAttributeMaxDynamicSharedMemorySize, SMEM_BN128);
    cudaFuncSetAttribute(hgemm_kernel<128, 32, 32, 32, 1, 2, 4>,
                         cudaFuncAttributeMaxDynamicSharedMemorySize, SMEM_F1);
    cudaFuncSetAttribute(bones_kernel,
                         cudaFuncAttributeMaxDynamicSharedMemorySize, SMEM_BONES);

    // main stream: prep (everything depends on it)
    prep_kernel<<<2412, 256>>>(features, X, dW1, W1t, dW2, W2t, cW1, cW1T, db3, dep);
    cudaEventRecord(evPrep, 0);

    // side stream: F1 = X @ cW1[4:] + cb1 (independent of gemm1/gemm2) — overlaps them
    cudaStreamWaitEvent(s2, evPrep, 0);
    hgemm_kernel<128, 32, 32, 32, 1, 2, 4>
        <<<dim3(1, M_ROWS / 128), 128, SMEM_F1, s2>>>(X, cW1T, cb1, (void*)F1, nullptr,
                                                      32, FDIM);
    cudaEventRecord(evF1, s2);

    // main stream: h1 = relu(X @ dW1 + db1)
    hgemm_kernel<128, 128, 64, 64, 0, 2, 3>
        <<<dim3(HDIM / 128, M_ROWS / 128), 128, SMEM_BN128>>>(X, W1t, db1, (void*)h1, nullptr,
                                                              HDIM, FDIM);
    // main stream: depth += relu(h1 @ dW2 + db2) @ dW3 (fused)
    hgemm_kernel<128, 128, 64, 64, 2, 2, 3>
        <<<dim3((HDIM / 2) / 128, M_ROWS / 128), 128, SMEM_BN128>>>(h1, W2t, db2, (void*)dep, dW3,
                                                                    HDIM / 2, HDIM);

    // join: bones needs both depth (main) and F1 (side)
    cudaStreamWaitEvent(0, evF1, 0);
    bones_kernel<<<BATCH / NB, 512, SMEM_BONES>>>(poses2d, confid, dep, F1, cW1, cW2, cb2, cW3,
                                                  cb3, out);
}

// round 16
// speedup vs baseline: 1.1027x; 1.0027x over previous
#include <cuda_runtime.h>
#include <cuda_bf16.h>
#include <cstdint>

#define DINLINE __device__ __forceinline__

// ---------------- problem constants ----------------
static constexpr int BATCH = 8192;
static constexpr int J = 25;
static constexpr int FDIM = 512;
static constexpr int HDIM = 1024;
static constexpr long M_ROWS = (long)BATCH * J;   // 204800

// ---------------- scratch (device globals; no cudaMalloc allowed) ----------------
__device__ __nv_bfloat16 g_X[M_ROWS * FDIM];          // features bf16      [204800,512]
__device__ __nv_bfloat16 g_W1t[HDIM * FDIM];          // dW1^T bf16         [1024,512]
__device__ __nv_bfloat16 g_W2t[FDIM * HDIM];          // dW2^T bf16         [512,1024]
__device__ __nv_bfloat16 g_cW1T[32 * FDIM];           // cW1[4:]^T bf16     [32,512]
__device__ __nv_bfloat16 g_h1[M_ROWS * HDIM];         // relu(X@W1+b1)      [204800,1024]
__device__ float g_F1[M_ROWS * 32];                   // features@cW1f+cb1  [204800,32]
__device__ float g_depth[M_ROWS];                     // [204800]

__constant__ int c_PAR[16] = {0, 0, 0, 0, 0, 0, 5, 7, 6, 8, 5, 6, 11, 13, 12, 14};
__constant__ int c_CHI[16] = {1, 2, 3, 4, 5, 6, 7, 9, 8, 10, 11, 12, 13, 15, 14, 16};

// ---------------- PTX helpers (sm_80-level only; virtual arch is compute_103) ----------------
DINLINE uint32_t smem_u32(const void* p) {
    uint32_t a;
    asm("{ .reg .u64 t; cvta.to.shared.u64 t, %1; cvt.u32.u64 %0, t; }" : "=r"(a) : "l"(p));
    return a;
}
DINLINE uint32_t sw128(uint32_t off) { return off ^ ((off >> 3) & 0x70); }

DINLINE void cp_async16_cg(uint32_t dst, const void* src) {
    asm volatile(
        "{ .reg .u64 g; cvta.to.global.u64 g, %1; cp.async.cg.shared.global [%0], [g], 16; }"
        :: "r"(dst), "l"(src));
}
DINLINE void cp_async16_ca(uint32_t dst, const void* src) {
    asm volatile(
        "{ .reg .u64 g; cvta.to.global.u64 g, %1; cp.async.ca.shared.global [%0], [g], 16; }"
        :: "r"(dst), "l"(src));
}
#define CP_COMMIT() asm volatile("cp.async.commit_group;" ::: "memory")
template <int N>
DINLINE void cp_wait() { asm volatile("cp.async.wait_group %0;" :: "n"(N) : "memory"); }

DINLINE void ldsm_x4(uint32_t (&r)[4], uint32_t addr) {
    asm volatile("ldmatrix.sync.aligned.m8n8.x4.shared.b16 {%0,%1,%2,%3}, [%4];"
                 : "=r"(r[0]), "=r"(r[1]), "=r"(r[2]), "=r"(r[3]) : "r"(addr));
}

DINLINE void mma16816(float (&c)[4], const uint32_t (&a)[4], uint32_t b0, uint32_t b1) {
    asm volatile(
        "mma.sync.aligned.m16n8k16.row.col.f32.bf16.bf16.f32 "
        "{%0,%1,%2,%3},{%4,%5,%6,%7},{%8,%9},{%0,%1,%2,%3};"
        : "+f"(c[0]), "+f"(c[1]), "+f"(c[2]), "+f"(c[3])
        : "r"(a[0]), "r"(a[1]), "r"(a[2]), "r"(a[3]), "r"(b0), "r"(b1));
}

// ---------------- fused prep kernel (block-range partitioned) ----------------
__global__ __launch_bounds__(256) void prep_kernel(
    const float* __restrict__ feat, __nv_bfloat16* __restrict__ X,
    const float* __restrict__ dW1, __nv_bfloat16* __restrict__ W1t,
    const float* __restrict__ dW2, __nv_bfloat16* __restrict__ W2t,
    const float* __restrict__ cW1, __nv_bfloat16* __restrict__ cW1T,
    const float* __restrict__ db3, float* __restrict__ depth) {
    int b = blockIdx.x, tid = threadIdx.x;
    if (b < 2048) {
        long n4 = M_ROWS * FDIM / 4;
        for (long i = (long)b * 256 + tid; i < n4; i += 2048L * 256) {
            float4 v = reinterpret_cast<const float4*>(feat)[i];
            __nv_bfloat162 a = __floats2bfloat162_rn(v.x, v.y);
            __nv_bfloat162 c = __floats2bfloat162_rn(v.z, v.w);
            uint2 u;
            u.x = *reinterpret_cast<uint32_t*>(&a);
            u.y = *reinterpret_cast<uint32_t*>(&c);
            reinterpret_cast<uint2*>(X)[i] = u;
        }
    } else if (b < 2176) {
        int bb = b - 2048;
        for (int idx = bb * 256 + tid; idx < 512 * 1024; idx += 128 * 256) {
            int k = idx & 511, n = idx >> 9;
            W1t[idx] = __float2bfloat16(dW1[k * 1024 + n]);
        }
    } else if (b < 2304) {
        int bb = b - 2176;
        for (int idx = bb * 256 + tid; idx < 1024 * 512; idx += 128 * 256) {
            int k = idx & 1023, n = idx >> 10;
            W2t[idx] = __float2bfloat16(dW2[k * 512 + n]);
        }
    } else if (b < 2312) {
        int bb = b - 2304;
        const float* src = cW1 + 4 * 32;
        for (int idx = bb * 256 + tid; idx < 512 * 32; idx += 8 * 256) {
            int k = idx & 511, n = idx >> 9;
            cW1T[idx] = __float2bfloat16(src[k * 32 + n]);
        }
    } else {
        int bb = b - 2312;
        float v = db3[0];
        for (long i = (long)bb * 256 + tid; i < M_ROWS; i += 100L * 256) depth[i] = v;
    }
}

// ---------------- HMMA GEMM: C = act(A[M,K] @ Bt[Ntot,K]^T + bias) ----------------
// R13 configuration for big GEMMs. BM/BN templated; BK=64, NSTAGE cp.async
// pipeline, MINB CTAs/SM. A loads .cg, B loads .ca.
// OUTMODE: 0 = relu -> bf16 store, 1 = linear -> fp32 store,
//          2 = relu -> fused dot with w3 + atomicAdd into depth (no C store).
template <int THREADS, int BM, int BN, int WM, int WN, int OUTMODE, int NSTAGE, int MINB>
__global__ __launch_bounds__(THREADS, MINB)
void hgemm_kernel(const __nv_bfloat16* __restrict__ A, const __nv_bfloat16* __restrict__ Bt,
                  const float* __restrict__ bias, void* __restrict__ Cout,
                  const float* __restrict__ w3, int Ntot, int KTOT) {
    constexpr int NWARP = THREADS / 32;
    constexpr int WARPS_M = BM / WM, WARPS_N = BN / WN;
    static_assert(WARPS_M * WARPS_N == NWARP, "warp layout mismatch");
    constexpr int MF = WM / 16;
    constexpr int NT8 = WN / 8;
    constexpr int NG = WN / 16;
    constexpr int ST_A = BM * 128;
    constexpr int ST_B = BN * 128;
    constexpr int ST = ST_A + ST_B;
    constexpr int A_ITERS = BM * 8 / THREADS;
    constexpr int B_ITERS = BN * 8 / THREADS;

    extern __shared__ char smem[];
    __shared__ float sbias[BN];
    __shared__ float sw3[BN];
    uint32_t sb = smem_u32(smem);
    int tid = threadIdx.x, lane = tid & 31, wid = tid >> 5;
    int warpM = wid % WARPS_M, warpN = wid / WARPS_M;
    long m0 = (long)blockIdx.y * BM;
    int n0 = blockIdx.x * BN;

    for (int i = tid; i < BN; i += THREADS) {
        sbias[i] = bias[n0 + i];
        if (OUTMODE == 2) sw3[i] = w3[n0 + i];
    }

    const __nv_bfloat16* Ag = A + m0 * KTOT;
    const __nv_bfloat16* Bg = Bt + (long)n0 * KTOT;

    int aE[A_ITERS];
    uint32_t aD[A_ITERS];
#pragma unroll
    for (int i = 0; i < A_ITERS; i++) {
        int idx = tid + i * THREADS, row = idx >> 3, seg = idx & 7;
        aE[i] = row * KTOT + seg * 8;
        aD[i] = sw128((uint32_t)(row * 128 + seg * 16));
    }
    int bE[B_ITERS];
    uint32_t bD[B_ITERS];
#pragma unroll
    for (int i = 0; i < B_ITERS; i++) {
        int idx = tid + i * THREADS, row = idx >> 3, seg = idx & 7;
        bE[i] = row * KTOT + seg * 8;
        bD[i] = ST_A + sw128((uint32_t)(row * 128 + seg * 16));
    }

    auto load_stage = [&](int buf, int kt) {
        uint32_t base = sb + buf * ST;
        int ke = kt * 64;
#pragma unroll
        for (int i = 0; i < A_ITERS; i++) cp_async16_cg(base + aD[i], Ag + ke + aE[i]);
#pragma unroll
        for (int i = 0; i < B_ITERS; i++) cp_async16_ca(base + bD[i], Bg + ke + bE[i]);
        CP_COMMIT();
    };

    uint32_t hi16 = (uint32_t)((lane >> 4) << 4);
    uint32_t aRow[MF], aXm[MF];
#pragma unroll
    for (int mf = 0; mf < MF; mf++) {
        int row = warpM * WM + mf * 16 + (lane & 15);
        aRow[mf] = (uint32_t)(row * 128);
        aXm[mf] = (uint32_t)((row & 7) << 4);
    }
    uint32_t bRow[NG], bXm[NG];
#pragma unroll
    for (int ng = 0; ng < NG; ng++) {
        int row = warpN * WN + ng * 16 + (lane & 15);
        bRow[ng] = (uint32_t)(ST_A + row * 128);
        bXm[ng] = (uint32_t)((row & 7) << 4);
    }

    float acc[MF][NT8][4];
#pragma unroll
    for (int mf = 0; mf < MF; mf++)
#pragma unroll
        for (int nt = 0; nt < NT8; nt++)
#pragma unroll
            for (int q = 0; q < 4; q++) acc[mf][nt][q] = 0.f;

    int KT = KTOT / 64;
#pragma unroll
    for (int s = 0; s < NSTAGE - 1; s++) load_stage(s, s);

    for (int kt = 0; kt < KT; kt++) {
        int buf = kt % NSTAGE;
        cp_wait<NSTAGE - 2>();
        __syncthreads();
        if (kt + NSTAGE - 1 < KT) load_stage((kt + NSTAGE - 1) % NSTAGE, kt + NSTAGE - 1);
        else CP_COMMIT();  // keep group count uniform so wait_group guards stage kt

        uint32_t base = sb + buf * ST;
#pragma unroll
        for (int ks = 0; ks < 4; ks++) {
            uint32_t a[MF][4];
            uint32_t b[NT8][2];
            uint32_t kofs = ((uint32_t)(ks * 32)) | hi16;
#pragma unroll
            for (int mf = 0; mf < MF; mf++)
                ldsm_x4(a[mf], base + aRow[mf] + (kofs ^ aXm[mf]));
#pragma unroll
            for (int ng = 0; ng < NG; ng++) {
                uint32_t r[4];
                ldsm_x4(r, base + bRow[ng] + (kofs ^ bXm[ng]));
                b[2 * ng][0] = r[0]; b[2 * ng][1] = r[2];
                b[2 * ng + 1][0] = r[1]; b[2 * ng + 1][1] = r[3];
            }
#pragma unroll
            for (int mf = 0; mf < MF; mf++)
#pragma unroll
                for (int nt = 0; nt < NT8; nt++)
                    mma16816(acc[mf][nt], a[mf], b[nt][0], b[nt][1]);
        }
    }
    __syncthreads();

    // epilogue
#pragma unroll
    for (int mf = 0; mf < MF; mf++) {
        long r0 = m0 + warpM * WM + mf * 16 + (lane >> 2);
        float p0 = 0.f, p1 = 0.f;
#pragma unroll
        for (int nt = 0; nt < NT8; nt++) {
            int cb = warpN * WN + nt * 8 + (lane & 3) * 2;
            float v0 = acc[mf][nt][0] + sbias[cb];
            float v1 = acc[mf][nt][1] + sbias[cb + 1];
            float v2 = acc[mf][nt][2] + sbias[cb];
            float v3 = acc[mf][nt][3] + sbias[cb + 1];
            if (OUTMODE != 1) {
                v0 = fmaxf(v0, 0.f); v1 = fmaxf(v1, 0.f);
                v2 = fmaxf(v2, 0.f); v3 = fmaxf(v3, 0.f);
            }
            if (OUTMODE == 0) {
                __nv_bfloat16* out = reinterpret_cast<__nv_bfloat16*>(Cout);
                __nv_bfloat162 h0 = __floats2bfloat162_rn(v0, v1);
                __nv_bfloat162 h1 = __floats2bfloat162_rn(v2, v3);
                *reinterpret_cast<uint32_t*>(out + r0 * Ntot + n0 + cb) =
                    *reinterpret_cast<uint32_t*>(&h0);
                *reinterpret_cast<uint32_t*>(out + (r0 + 8) * Ntot + n0 + cb) =
                    *reinterpret_cast<uint32_t*>(&h1);
            } else if (OUTMODE == 1) {
                float* out = reinterpret_cast<float*>(Cout);
                *reinterpret_cast<float2*>(out + r0 * Ntot + n0 + cb) = make_float2(v0, v1);
                *reinterpret_cast<float2*>(out + (r0 + 8) * Ntot + n0 + cb) = make_float2(v2, v3);
            } else {
                float w0 = sw3[cb], w1 = sw3[cb + 1];
                p0 = fmaf(v0, w0, fmaf(v1, w1, p0));
                p1 = fmaf(v2, w0, fmaf(v3, w1, p1));
            }
        }
        if (OUTMODE == 2) {
            p0 += __shfl_xor_sync(0xffffffffu, p0, 1);
            p0 += __shfl_xor_sync(0xffffffffu, p0, 2);
            p1 += __shfl_xor_sync(0xffffffffu, p1, 1);
            p1 += __shfl_xor_sync(0xffffffffu, p1, 2);
            if ((lane & 3) == 0) {
                float* depth = reinterpret_cast<float*>(Cout);
                atomicAdd(depth + r0, p0);
                atomicAdd(depth + r0 + 8, p1);
            }
        }
    }
}

// ---------------- bone refinement: NB bodies per block, 1 warp per bone ----------------
static constexpr int NB = 16;  // bodies per block
__global__ __launch_bounds__(512) void bones_kernel(
    const float* __restrict__ poses2d, const float* __restrict__ confid,
    const float* __restrict__ depth, const float* __restrict__ F1,
    const float* __restrict__ cW1, const float* __restrict__ cW2,
    const float* __restrict__ cb2, const float* __restrict__ cW3,
    const float* __restrict__ cb3, float* __restrict__ out) {
    extern __shared__ float sm[];
    float* sp = sm;                 // NB*75
    float* sc = sp + NB * 75;       // NB*25
    float* sbf = sc + NB * 25;      // NB*48
    float* supd = sbf + NB * 48;    // NB*3
    float* sW2 = supd + NB * 3;     // 2048
    float* spre = sW2 + 2048;       // 16*NB*32

    int tid = threadIdx.x, wid = tid >> 5, lane = tid & 31;
    long base = (long)blockIdx.x * NB;

    for (int i = tid; i < 2048; i += 512) sW2[i] = cW2[i];
    for (int idx = tid; idx < NB * 25; idx += 512) {
        long row = base * 25 + idx;
        sc[idx] = confid[row];
        sp[idx * 3 + 0] = poses2d[row * 2 + 0];
        sp[idx * 3 + 1] = poses2d[row * 2 + 1];
        sp[idx * 3 + 2] = depth[row];
    }
    int e = wid;
    int pj = c_PAR[e], cj = c_CHI[e];
    for (int b = 0; b < NB; b++) {
        spre[(e * NB + b) * 32 + lane] =
            0.5f * (F1[((base + b) * 25 + pj) * 32 + lane] +
                    F1[((base + b) * 25 + cj) * 32 + lane]);
    }
    float w1k0 = cW1[0 * 32 + lane], w1k1 = cW1[1 * 32 + lane];
    float w1k2 = cW1[2 * 32 + lane], w1k3 = cW1[3 * 32 + lane];
    float w30 = cW3[(2 * lane) * 3 + 0], w31 = cW3[(2 * lane) * 3 + 1], w32 = cW3[(2 * lane) * 3 + 2];
    float w33 = cW3[(2 * lane + 1) * 3 + 0], w34 = cW3[(2 * lane + 1) * 3 + 1], w35 = cW3[(2 * lane + 1) * 3 + 2];
    float c2a = cb2[2 * lane], c2b = cb2[2 * lane + 1];
    __syncthreads();

    float w2a[32], w2b[32];
#pragma unroll
    for (int i = 0; i < 32; i++) {
        w2a[i] = sW2[i * 64 + 2 * lane];
        w2b[i] = sW2[i * 64 + 2 * lane + 1];
    }

    for (int it = 0; it < 3; it++) {
        for (int b = 0; b < NB; b++) {
            const float* spb = sp + b * 75;
            float vx = spb[cj * 3 + 0] - spb[pj * 3 + 0];
            float vy = spb[cj * 3 + 1] - spb[pj * 3 + 1];
            float vz = spb[cj * 3 + 2] - spb[pj * 3 + 2];
            float len = sqrtf(vx * vx + vy * vy + vz * vz);
            float inv = 1.0f / (len + 1e-8f);
            float pre = spre[(e * NB + b) * 32 + lane];
            float g1 = fmaxf(pre + vx * inv * w1k0 + vy * inv * w1k1 + vz * inv * w1k2 + len * w1k3, 0.f);
            float a0 = c2a, a1 = c2b;
#pragma unroll
            for (int i = 0; i < 32; i++) {
                float g = __shfl_sync(0xffffffffu, g1, i);
                a0 = fmaf(g, w2a[i], a0);
                a1 = fmaf(g, w2b[i], a1);
            }
            a0 = fmaxf(a0, 0.f);
            a1 = fmaxf(a1, 0.f);
            float f0 = a0 * w30 + a1 * w33;
            float f1 = a0 * w31 + a1 * w34;
            float f2 = a0 * w32 + a1 * w35;
#pragma unroll
            for (int o = 16; o; o >>= 1) {
                f0 += __shfl_xor_sync(0xffffffffu, f0, o);
                f1 += __shfl_xor_sync(0xffffffffu, f1, o);
                f2 += __shfl_xor_sync(0xffffffffu, f2, o);
            }
            if (lane == 0) {
                sbf[b * 48 + e * 3 + 0] = f0;
                sbf[b * 48 + e * 3 + 1] = f1;
                sbf[b * 48 + e * 3 + 2] = f2;
            }
        }
        __syncthreads();
        if (tid < NB * 3) {
            int body = tid / 3, k = tid % 3;
            float s = 0.f;
            for (int q = 0; q < 16; q++) s += sbf[body * 48 + q * 3 + k];
            supd[tid] = cb3[k] + s * (1.0f / 16.0f);
        }
        __syncthreads();
        for (int idx = tid; idx < NB * 75; idx += 512) {
            int body = idx / 75, r = idx % 75, j = r / 3, k = r % 3;
            sp[idx] = (sp[idx] + 0.1f * supd[body * 3 + k]) * sc[body * 25 + j];
        }
        __syncthreads();
    }
    for (int idx = tid; idx < NB * 75; idx += 512) out[base * 75 + idx] = sp[idx];
}

// ---------------- launcher ----------------
extern "C" void kernel_launch(void* const* d_in, const int* in_sizes, int n_in,
                              void* d_out, int out_size) {
    const float* poses2d = (const float*)d_in[0];
    const float* features = (const float*)d_in[1];
    const float* confid = (const float*)d_in[2];
    const float* dW1 = (const float*)d_in[3];
    const float* db1 = (const float*)d_in[4];
    const float* dW2 = (const float*)d_in[5];
    const float* db2 = (const float*)d_in[6];
    const float* dW3 = (const float*)d_in[7];
    const float* db3 = (const float*)d_in[8];
    const float* cW1 = (const float*)d_in[9];
    const float* cb1 = (const float*)d_in[10];
    const float* cW2 = (const float*)d_in[11];
    const float* cb2 = (const float*)d_in[12];
    const float* cW3 = (const float*)d_in[13];
    const float* cb3 = (const float*)d_in[14];
    float* out = (float*)d_out;

    __nv_bfloat16 *X, *W1t, *W2t, *cW1T, *h1;
    float *F1, *dep;
    cudaGetSymbolAddress((void**)&X, g_X);
    cudaGetSymbolAddress((void**)&W1t, g_W1t);
    cudaGetSymbolAddress((void**)&W2t, g_W2t);
    cudaGetSymbolAddress((void**)&cW1T, g_cW1T);
    cudaGetSymbolAddress((void**)&h1, g_h1);
    cudaGetSymbolAddress((void**)&F1, g_F1);
    cudaGetSymbolAddress((void**)&dep, g_depth);

    // lazy-created side stream + events (handles reused every call)
    static cudaStream_t s2 = nullptr;
    static cudaEvent_t evPrep = nullptr, evF1 = nullptr;
    if (!s2) {
        cudaStreamCreateWithFlags(&s2, cudaStreamNonBlocking);
        cudaEventCreateWithFlags(&evPrep, cudaEventDisableTiming);
        cudaEventCreateWithFlags(&evF1, cudaEventDisableTiming);
    }

    constexpr int SMEM_BN128 = 2 * (128 * 128 + 128 * 128);  // 65536, MINB=3
    constexpr int SMEM_F1 = 2 * (64 * 128 + 32 * 128);       // 24576 -> fits 36KB hole
    constexpr int SMEM_BONES = (NB * 75 + NB * 25 + NB * 48 + NB * 3 + 2048 + 16 * NB * 32) * 4;

    cudaFuncSetAttribute(hgemm_kernel<128, 128, 128, 64, 64, 0, 2, 3>,
                         cudaFuncAttributeMaxDynamicSharedMemorySize, SMEM_BN128);
    cudaFuncSetAttribute(hgemm_kernel<128, 128, 128, 64, 64, 2, 2, 3>,
                         cudaFuncAttributeMaxDynamicSharedMemorySize, SMEM_BN128);
    cudaFuncSetAttribute(hgemm_kernel<64, 64, 32, 32, 32, 1, 2, 4>,
                         cudaFuncAttributeMaxDynamicSharedMemorySize, SMEM_F1);
    cudaFuncSetAttribute(bones_kernel,
                         cudaFuncAttributeMaxDynamicSharedMemorySize, SMEM_BONES);

    // main stream: prep (everything depends on it)
    prep_kernel<<<2412, 256>>>(features, X, dW1, W1t, dW2, W2t, cW1, cW1T, db3, dep);
    cudaEventRecord(evPrep, 0);

    // side stream: F1 = X @ cW1[4:] + cb1 — 24KB CTAs co-resident with gemm1's
    // 3x64KB, so F1 genuinely overlaps the big GEMMs.
    cudaStreamWaitEvent(s2, evPrep, 0);
    hgemm_kernel<64, 64, 32, 32, 32, 1, 2, 4>
        <<<dim3(1, M_ROWS / 64), 64, SMEM_F1, s2>>>(X, cW1T, cb1, (void*)F1, nullptr,
                                                    32, FDIM);
    cudaEventRecord(evF1, s2);

    // main stream: h1 = relu(X @ dW1 + db1)
    hgemm_kernel<128, 128, 128, 64, 64, 0, 2, 3>
        <<<dim3(HDIM / 128, M_ROWS / 128), 128, SMEM_BN128>>>(X, W1t, db1, (void*)h1, nullptr,
                                                              HDIM, FDIM);
    // main stream: depth += relu(h1 @ dW2 + db2) @ dW3 (fused)
    hgemm_kernel<128, 128, 128, 64, 64, 2, 2, 3>
        <<<dim3((HDIM / 2) / 128, M_ROWS / 128), 128, SMEM_BN128>>>(h1, W2t, db2, (void*)dep, dW3,
                                                                    HDIM / 2, HDIM);

    // join: bones needs both depth (main) and F1 (side)
    cudaStreamWaitEvent(0, evF1, 0);
    bones_kernel<<<BATCH / NB, 512, SMEM_BONES>>>(poses2d, confid, dep, F1, cW1, cW2, cb2, cW3,
                                                  cb3, out);
}

// round 17
// speedup vs baseline: 1.1071x; 1.0040x over previous
#include <cuda_runtime.h>
#include <cuda_bf16.h>
#include <cstdint>

#define DINLINE __device__ __forceinline__

// ---------------- problem constants ----------------
static constexpr int BATCH = 8192;
static constexpr int J = 25;
static constexpr int FDIM = 512;
static constexpr int HDIM = 1024;
static constexpr long M_ROWS = (long)BATCH * J;   // 204800

// ---------------- scratch (device globals; no cudaMalloc allowed) ----------------
__device__ __nv_bfloat16 g_X[M_ROWS * FDIM];          // features bf16      [204800,512]
__device__ __nv_bfloat16 g_W1t[HDIM * FDIM];          // dW1^T bf16         [1024,512]
__device__ __nv_bfloat16 g_W2t[FDIM * HDIM];          // dW2^T bf16         [512,1024]
__device__ __nv_bfloat16 g_cW1T[32 * FDIM];           // cW1[4:]^T bf16     [32,512]
__device__ __nv_bfloat16 g_h1[M_ROWS * HDIM];         // relu(X@W1+b1)      [204800,1024]
__device__ float g_F1[M_ROWS * 32];                   // features@cW1f+cb1  [204800,32]
__device__ float g_depth[M_ROWS];                     // [204800]

__constant__ int c_PAR[16] = {0, 0, 0, 0, 0, 0, 5, 7, 6, 8, 5, 6, 11, 13, 12, 14};
__constant__ int c_CHI[16] = {1, 2, 3, 4, 5, 6, 7, 9, 8, 10, 11, 12, 13, 15, 14, 16};

// ---------------- PTX helpers (sm_80-level only; virtual arch is compute_103) ----------------
DINLINE uint32_t smem_u32(const void* p) {
    uint32_t a;
    asm("{ .reg .u64 t; cvta.to.shared.u64 t, %1; cvt.u32.u64 %0, t; }" : "=r"(a) : "l"(p));
    return a;
}
DINLINE uint32_t sw128(uint32_t off) { return off ^ ((off >> 3) & 0x70); }

DINLINE void cp_async16_cg(uint32_t dst, const void* src) {
    asm volatile(
        "{ .reg .u64 g; cvta.to.global.u64 g, %1; cp.async.cg.shared.global [%0], [g], 16; }"
        :: "r"(dst), "l"(src));
}
DINLINE void cp_async16_ca(uint32_t dst, const void* src) {
    asm volatile(
        "{ .reg .u64 g; cvta.to.global.u64 g, %1; cp.async.ca.shared.global [%0], [g], 16; }"
        :: "r"(dst), "l"(src));
}
#define CP_COMMIT() asm volatile("cp.async.commit_group;" ::: "memory")
template <int N>
DINLINE void cp_wait() { asm volatile("cp.async.wait_group %0;" :: "n"(N) : "memory"); }

DINLINE void ldsm_x4(uint32_t (&r)[4], uint32_t addr) {
    asm volatile("ldmatrix.sync.aligned.m8n8.x4.shared.b16 {%0,%1,%2,%3}, [%4];"
                 : "=r"(r[0]), "=r"(r[1]), "=r"(r[2]), "=r"(r[3]) : "r"(addr));
}

DINLINE void mma16816(float (&c)[4], const uint32_t (&a)[4], uint32_t b0, uint32_t b1) {
    asm volatile(
        "mma.sync.aligned.m16n8k16.row.col.f32.bf16.bf16.f32 "
        "{%0,%1,%2,%3},{%4,%5,%6,%7},{%8,%9},{%0,%1,%2,%3};"
        : "+f"(c[0]), "+f"(c[1]), "+f"(c[2]), "+f"(c[3])
        : "r"(a[0]), "r"(a[1]), "r"(a[2]), "r"(a[3]), "r"(b0), "r"(b1));
}

// ---------------- fused prep kernel (block-range partitioned) ----------------
__global__ __launch_bounds__(256) void prep_kernel(
    const float* __restrict__ feat, __nv_bfloat16* __restrict__ X,
    const float* __restrict__ dW1, __nv_bfloat16* __restrict__ W1t,
    const float* __restrict__ dW2, __nv_bfloat16* __restrict__ W2t,
    const float* __restrict__ cW1, __nv_bfloat16* __restrict__ cW1T,
    const float* __restrict__ db3, float* __restrict__ depth) {
    int b = blockIdx.x, tid = threadIdx.x;
    if (b < 2048) {
        long n4 = M_ROWS * FDIM / 4;
        for (long i = (long)b * 256 + tid; i < n4; i += 2048L * 256) {
            float4 v = reinterpret_cast<const float4*>(feat)[i];
            __nv_bfloat162 a = __floats2bfloat162_rn(v.x, v.y);
            __nv_bfloat162 c = __floats2bfloat162_rn(v.z, v.w);
            uint2 u;
            u.x = *reinterpret_cast<uint32_t*>(&a);
            u.y = *reinterpret_cast<uint32_t*>(&c);
            reinterpret_cast<uint2*>(X)[i] = u;
        }
    } else if (b < 2176) {
        int bb = b - 2048;
        for (int idx = bb * 256 + tid; idx < 512 * 1024; idx += 128 * 256) {
            int k = idx & 511, n = idx >> 9;
            W1t[idx] = __float2bfloat16(dW1[k * 1024 + n]);
        }
    } else if (b < 2304) {
        int bb = b - 2176;
        for (int idx = bb * 256 + tid; idx < 1024 * 512; idx += 128 * 256) {
            int k = idx & 1023, n = idx >> 10;
            W2t[idx] = __float2bfloat16(dW2[k * 512 + n]);
        }
    } else if (b < 2312) {
        int bb = b - 2304;
        const float* src = cW1 + 4 * 32;
        for (int idx = bb * 256 + tid; idx < 512 * 32; idx += 8 * 256) {
            int k = idx & 511, n = idx >> 9;
            cW1T[idx] = __float2bfloat16(src[k * 32 + n]);
        }
    } else {
        int bb = b - 2312;
        float v = db3[0];
        for (long i = (long)bb * 256 + tid; i < M_ROWS; i += 100L * 256) depth[i] = v;
    }
}

// ---------------- HMMA GEMM: C = act(A[M,K] @ Bt[Ntot,K]^T + bias) ----------------
// R13 configuration for big GEMMs. BM/BN templated; BK=64, NSTAGE cp.async
// pipeline, MINB CTAs/SM. A loads .cg, B loads .ca.
// REV: reverse row-tile order so this kernel starts on the A rows its producer
// wrote LAST (still L2-resident) — pure index permutation, math unchanged.
// OUTMODE: 0 = relu -> bf16 store, 1 = linear -> fp32 store,
//          2 = relu -> fused dot with w3 + atomicAdd into depth (no C store).
template <int THREADS, int BM, int BN, int WM, int WN, int OUTMODE, int NSTAGE, int MINB, int REV>
__global__ __launch_bounds__(THREADS, MINB)
void hgemm_kernel(const __nv_bfloat16* __restrict__ A, const __nv_bfloat16* __restrict__ Bt,
                  const float* __restrict__ bias, void* __restrict__ Cout,
                  const float* __restrict__ w3, int Ntot, int KTOT) {
    constexpr int NWARP = THREADS / 32;
    constexpr int WARPS_M = BM / WM, WARPS_N = BN / WN;
    static_assert(WARPS_M * WARPS_N == NWARP, "warp layout mismatch");
    constexpr int MF = WM / 16;
    constexpr int NT8 = WN / 8;
    constexpr int NG = WN / 16;
    constexpr int ST_A = BM * 128;
    constexpr int ST_B = BN * 128;
    constexpr int ST = ST_A + ST_B;
    constexpr int A_ITERS = BM * 8 / THREADS;
    constexpr int B_ITERS = BN * 8 / THREADS;

    extern __shared__ char smem[];
    __shared__ float sbias[BN];
    __shared__ float sw3[BN];
    uint32_t sb = smem_u32(smem);
    int tid = threadIdx.x, lane = tid & 31, wid = tid >> 5;
    int warpM = wid % WARPS_M, warpN = wid / WARPS_M;
    int byi = REV ? (int)(gridDim.y - 1 - blockIdx.y) : (int)blockIdx.y;
    long m0 = (long)byi * BM;
    int n0 = blockIdx.x * BN;

    for (int i = tid; i < BN; i += THREADS) {
        sbias[i] = bias[n0 + i];
        if (OUTMODE == 2) sw3[i] = w3[n0 + i];
    }

    const __nv_bfloat16* Ag = A + m0 * KTOT;
    const __nv_bfloat16* Bg = Bt + (long)n0 * KTOT;

    int aE[A_ITERS];
    uint32_t aD[A_ITERS];
#pragma unroll
    for (int i = 0; i < A_ITERS; i++) {
        int idx = tid + i * THREADS, row = idx >> 3, seg = idx & 7;
        aE[i] = row * KTOT + seg * 8;
        aD[i] = sw128((uint32_t)(row * 128 + seg * 16));
    }
    int bE[B_ITERS];
    uint32_t bD[B_ITERS];
#pragma unroll
    for (int i = 0; i < B_ITERS; i++) {
        int idx = tid + i * THREADS, row = idx >> 3, seg = idx & 7;
        bE[i] = row * KTOT + seg * 8;
        bD[i] = ST_A + sw128((uint32_t)(row * 128 + seg * 16));
    }

    auto load_stage = [&](int buf, int kt) {
        uint32_t base = sb + buf * ST;
        int ke = kt * 64;
#pragma unroll
        for (int i = 0; i < A_ITERS; i++) cp_async16_cg(base + aD[i], Ag + ke + aE[i]);
#pragma unroll
        for (int i = 0; i < B_ITERS; i++) cp_async16_ca(base + bD[i], Bg + ke + bE[i]);
        CP_COMMIT();
    };

    uint32_t hi16 = (uint32_t)((lane >> 4) << 4);
    uint32_t aRow[MF], aXm[MF];
#pragma unroll
    for (int mf = 0; mf < MF; mf++) {
        int row = warpM * WM + mf * 16 + (lane & 15);
        aRow[mf] = (uint32_t)(row * 128);
        aXm[mf] = (uint32_t)((row & 7) << 4);
    }
    uint32_t bRow[NG], bXm[NG];
#pragma unroll
    for (int ng = 0; ng < NG; ng++) {
        int row = warpN * WN + ng * 16 + (lane & 15);
        bRow[ng] = (uint32_t)(ST_A + row * 128);
        bXm[ng] = (uint32_t)((row & 7) << 4);
    }

    float acc[MF][NT8][4];
#pragma unroll
    for (int mf = 0; mf < MF; mf++)
#pragma unroll
        for (int nt = 0; nt < NT8; nt++)
#pragma unroll
            for (int q = 0; q < 4; q++) acc[mf][nt][q] = 0.f;

    int KT = KTOT / 64;
#pragma unroll
    for (int s = 0; s < NSTAGE - 1; s++) load_stage(s, s);

    for (int kt = 0; kt < KT; kt++) {
        int buf = kt % NSTAGE;
        cp_wait<NSTAGE - 2>();
        __syncthreads();
        if (kt + NSTAGE - 1 < KT) load_stage((kt + NSTAGE - 1) % NSTAGE, kt + NSTAGE - 1);
        else CP_COMMIT();  // keep group count uniform so wait_group guards stage kt

        uint32_t base = sb + buf * ST;
#pragma unroll
        for (int ks = 0; ks < 4; ks++) {
            uint32_t a[MF][4];
            uint32_t b[NT8][2];
            uint32_t kofs = ((uint32_t)(ks * 32)) | hi16;
#pragma unroll
            for (int mf = 0; mf < MF; mf++)
                ldsm_x4(a[mf], base + aRow[mf] + (kofs ^ aXm[mf]));
#pragma unroll
            for (int ng = 0; ng < NG; ng++) {
                uint32_t r[4];
                ldsm_x4(r, base + bRow[ng] + (kofs ^ bXm[ng]));
                b[2 * ng][0] = r[0]; b[2 * ng][1] = r[2];
                b[2 * ng + 1][0] = r[1]; b[2 * ng + 1][1] = r[3];
            }
#pragma unroll
            for (int mf = 0; mf < MF; mf++)
#pragma unroll
                for (int nt = 0; nt < NT8; nt++)
                    mma16816(acc[mf][nt], a[mf], b[nt][0], b[nt][1]);
        }
    }
    __syncthreads();

    // epilogue
#pragma unroll
    for (int mf = 0; mf < MF; mf++) {
        long r0 = m0 + warpM * WM + mf * 16 + (lane >> 2);
        float p0 = 0.f, p1 = 0.f;
#pragma unroll
        for (int nt = 0; nt < NT8; nt++) {
            int cb = warpN * WN + nt * 8 + (lane & 3) * 2;
            float v0 = acc[mf][nt][0] + sbias[cb];
            float v1 = acc[mf][nt][1] + sbias[cb + 1];
            float v2 = acc[mf][nt][2] + sbias[cb];
            float v3 = acc[mf][nt][3] + sbias[cb + 1];
            if (OUTMODE != 1) {
                v0 = fmaxf(v0, 0.f); v1 = fmaxf(v1, 0.f);
                v2 = fmaxf(v2, 0.f); v3 = fmaxf(v3, 0.f);
            }
            if (OUTMODE == 0) {
                __nv_bfloat16* out = reinterpret_cast<__nv_bfloat16*>(Cout);
                __nv_bfloat162 h0 = __floats2bfloat162_rn(v0, v1);
                __nv_bfloat162 h1 = __floats2bfloat162_rn(v2, v3);
                *reinterpret_cast<uint32_t*>(out + r0 * Ntot + n0 + cb) =
                    *reinterpret_cast<uint32_t*>(&h0);
                *reinterpret_cast<uint32_t*>(out + (r0 + 8) * Ntot + n0 + cb) =
                    *reinterpret_cast<uint32_t*>(&h1);
            } else if (OUTMODE == 1) {
                float* out = reinterpret_cast<float*>(Cout);
                *reinterpret_cast<float2*>(out + r0 * Ntot + n0 + cb) = make_float2(v0, v1);
                *reinterpret_cast<float2*>(out + (r0 + 8) * Ntot + n0 + cb) = make_float2(v2, v3);
            } else {
                float w0 = sw3[cb], w1 = sw3[cb + 1];
                p0 = fmaf(v0, w0, fmaf(v1, w1, p0));
                p1 = fmaf(v2, w0, fmaf(v3, w1, p1));
            }
        }
        if (OUTMODE == 2) {
            p0 += __shfl_xor_sync(0xffffffffu, p0, 1);
            p0 += __shfl_xor_sync(0xffffffffu, p0, 2);
            p1 += __shfl_xor_sync(0xffffffffu, p1, 1);
            p1 += __shfl_xor_sync(0xffffffffu, p1, 2);
            if ((lane & 3) == 0) {
                float* depth = reinterpret_cast<float*>(Cout);
                atomicAdd(depth + r0, p0);
                atomicAdd(depth + r0 + 8, p1);
            }
        }
    }
}

// ---------------- bone refinement: NB bodies per block, 1 warp per bone ----------------
static constexpr int NB = 16;  // bodies per block
__global__ __launch_bounds__(512) void bones_kernel(
    const float* __restrict__ poses2d, const float* __restrict__ confid,
    const float* __restrict__ depth, const float* __restrict__ F1,
    const float* __restrict__ cW1, const float* __restrict__ cW2,
    const float* __restrict__ cb2, const float* __restrict__ cW3,
    const float* __restrict__ cb3, float* __restrict__ out) {
    extern __shared__ float sm[];
    float* sp = sm;                 // NB*75
    float* sc = sp + NB * 75;       // NB*25
    float* sbf = sc + NB * 25;      // NB*48
    float* supd = sbf + NB * 48;    // NB*3
    float* sW2 = supd + NB * 3;     // 2048
    float* spre = sW2 + 2048;       // 16*NB*32

    int tid = threadIdx.x, wid = tid >> 5, lane = tid & 31;
    long base = (long)blockIdx.x * NB;

    for (int i = tid; i < 2048; i += 512) sW2[i] = cW2[i];
    for (int idx = tid; idx < NB * 25; idx += 512) {
        long row = base * 25 + idx;
        sc[idx] = confid[row];
        sp[idx * 3 + 0] = poses2d[row * 2 + 0];
        sp[idx * 3 + 1] = poses2d[row * 2 + 1];
        sp[idx * 3 + 2] = depth[row];
    }
    int e = wid;
    int pj = c_PAR[e], cj = c_CHI[e];
    for (int b = 0; b < NB; b++) {
        spre[(e * NB + b) * 32 + lane] =
            0.5f * (F1[((base + b) * 25 + pj) * 32 + lane] +
                    F1[((base + b) * 25 + cj) * 32 + lane]);
    }
    float w1k0 = cW1[0 * 32 + lane], w1k1 = cW1[1 * 32 + lane];
    float w1k2 = cW1[2 * 32 + lane], w1k3 = cW1[3 * 32 + lane];
    float w30 = cW3[(2 * lane) * 3 + 0], w31 = cW3[(2 * lane) * 3 + 1], w32 = cW3[(2 * lane) * 3 + 2];
    float w33 = cW3[(2 * lane + 1) * 3 + 0], w34 = cW3[(2 * lane + 1) * 3 + 1], w35 = cW3[(2 * lane + 1) * 3 + 2];
    float c2a = cb2[2 * lane], c2b = cb2[2 * lane + 1];
    __syncthreads();

    float w2a[32], w2b[32];
#pragma unroll
    for (int i = 0; i < 32; i++) {
        w2a[i] = sW2[i * 64 + 2 * lane];
        w2b[i] = sW2[i * 64 + 2 * lane + 1];
    }

    for (int it = 0; it < 3; it++) {
        for (int b = 0; b < NB; b++) {
            const float* spb = sp + b * 75;
            float vx = spb[cj * 3 + 0] - spb[pj * 3 + 0];
            float vy = spb[cj * 3 + 1] - spb[pj * 3 + 1];
            float vz = spb[cj * 3 + 2] - spb[pj * 3 + 2];
            float len = sqrtf(vx * vx + vy * vy + vz * vz);
            float inv = 1.0f / (len + 1e-8f);
            float pre = spre[(e * NB + b) * 32 + lane];
            float g1 = fmaxf(pre + vx * inv * w1k0 + vy * inv * w1k1 + vz * inv * w1k2 + len * w1k3, 0.f);
            float a0 = c2a, a1 = c2b;
#pragma unroll
            for (int i = 0; i < 32; i++) {
                float g = __shfl_sync(0xffffffffu, g1, i);
                a0 = fmaf(g, w2a[i], a0);
                a1 = fmaf(g, w2b[i], a1);
            }
            a0 = fmaxf(a0, 0.f);
            a1 = fmaxf(a1, 0.f);
            float f0 = a0 * w30 + a1 * w33;
            float f1 = a0 * w31 + a1 * w34;
            float f2 = a0 * w32 + a1 * w35;
#pragma unroll
            for (int o = 16; o; o >>= 1) {
                f0 += __shfl_xor_sync(0xffffffffu, f0, o);
                f1 += __shfl_xor_sync(0xffffffffu, f1, o);
                f2 += __shfl_xor_sync(0xffffffffu, f2, o);
            }
            if (lane == 0) {
                sbf[b * 48 + e * 3 + 0] = f0;
                sbf[b * 48 + e * 3 + 1] = f1;
                sbf[b * 48 + e * 3 + 2] = f2;
            }
        }
        __syncthreads();
        if (tid < NB * 3) {
            int body = tid / 3, k = tid % 3;
            float s = 0.f;
            for (int q = 0; q < 16; q++) s += sbf[body * 48 + q * 3 + k];
            supd[tid] = cb3[k] + s * (1.0f / 16.0f);
        }
        __syncthreads();
        for (int idx = tid; idx < NB * 75; idx += 512) {
            int body = idx / 75, r = idx % 75, j = r / 3, k = r % 3;
            sp[idx] = (sp[idx] + 0.1f * supd[body * 3 + k]) * sc[body * 25 + j];
        }
        __syncthreads();
    }
    for (int idx = tid; idx < NB * 75; idx += 512) out[base * 75 + idx] = sp[idx];
}

// ---------------- launcher ----------------
extern "C" void kernel_launch(void* const* d_in, const int* in_sizes, int n_in,
                              void* d_out, int out_size) {
    const float* poses2d = (const float*)d_in[0];
    const float* features = (const float*)d_in[1];
    const float* confid = (const float*)d_in[2];
    const float* dW1 = (const float*)d_in[3];
    const float* db1 = (const float*)d_in[4];
    const float* dW2 = (const float*)d_in[5];
    const float* db2 = (const float*)d_in[6];
    const float* dW3 = (const float*)d_in[7];
    const float* db3 = (const float*)d_in[8];
    const float* cW1 = (const float*)d_in[9];
    const float* cb1 = (const float*)d_in[10];
    const float* cW2 = (const float*)d_in[11];
    const float* cb2 = (const float*)d_in[12];
    const float* cW3 = (const float*)d_in[13];
    const float* cb3 = (const float*)d_in[14];
    float* out = (float*)d_out;

    __nv_bfloat16 *X, *W1t, *W2t, *cW1T, *h1;
    float *F1, *dep;
    cudaGetSymbolAddress((void**)&X, g_X);
    cudaGetSymbolAddress((void**)&W1t, g_W1t);
    cudaGetSymbolAddress((void**)&W2t, g_W2t);
    cudaGetSymbolAddress((void**)&cW1T, g_cW1T);
    cudaGetSymbolAddress((void**)&h1, g_h1);
    cudaGetSymbolAddress((void**)&F1, g_F1);
    cudaGetSymbolAddress((void**)&dep, g_depth);

    // lazy-created side stream + events (handles reused every call)
    static cudaStream_t s2 = nullptr;
    static cudaEvent_t evPrep = nullptr, evF1 = nullptr;
    if (!s2) {
        cudaStreamCreateWithFlags(&s2, cudaStreamNonBlocking);
        cudaEventCreateWithFlags(&evPrep, cudaEventDisableTiming);
        cudaEventCreateWithFlags(&evF1, cudaEventDisableTiming);
    }

    constexpr int SMEM_BN128 = 2 * (128 * 128 + 128 * 128);  // 65536, MINB=3
    constexpr int SMEM_F1 = 2 * (64 * 128 + 32 * 128);       // 24576 -> co-resident with gemm1
    constexpr int SMEM_BONES = (NB * 75 + NB * 25 + NB * 48 + NB * 3 + 2048 + 16 * NB * 32) * 4;

    cudaFuncSetAttribute(hgemm_kernel<128, 128, 128, 64, 64, 0, 2, 3, 1>,
                         cudaFuncAttributeMaxDynamicSharedMemorySize, SMEM_BN128);
    cudaFuncSetAttribute(hgemm_kernel<128, 128, 128, 64, 64, 2, 2, 3, 1>,
                         cudaFuncAttributeMaxDynamicSharedMemorySize, SMEM_BN128);
    cudaFuncSetAttribute(hgemm_kernel<64, 64, 32, 32, 32, 1, 2, 4, 0>,
                         cudaFuncAttributeMaxDynamicSharedMemorySize, SMEM_F1);
    cudaFuncSetAttribute(bones_kernel,
                         cudaFuncAttributeMaxDynamicSharedMemorySize, SMEM_BONES);

    // main stream: prep (everything depends on it)
    prep_kernel<<<2412, 256>>>(features, X, dW1, W1t, dW2, W2t, cW1, cW1T, db3, dep);
    cudaEventRecord(evPrep, 0);

    // side stream: F1 = X @ cW1[4:] + cb1 — ascending row order (reads the X region
    // gemm1, running in reverse, is not hammering)
    cudaStreamWaitEvent(s2, evPrep, 0);
    hgemm_kernel<64, 64, 32, 32, 32, 1, 2, 4, 0>
        <<<dim3(1, M_ROWS / 64), 64, SMEM_F1, s2>>>(X, cW1T, cb1, (void*)F1, nullptr,
                                                    32, FDIM);
    cudaEventRecord(evF1, s2);

    // main stream: h1 = relu(X @ dW1 + db1) — REVERSED row order: starts on the X
    // rows prep wrote last (L2-resident)
    hgemm_kernel<128, 128, 128, 64, 64, 0, 2, 3, 1>
        <<<dim3(HDIM / 128, M_ROWS / 128), 128, SMEM_BN128>>>(X, W1t, db1, (void*)h1, nullptr,
                                                              HDIM, FDIM);
    // main stream: depth += relu(h1 @ dW2 + db2) @ dW3 — REVERSED row order: starts
    // on the h1 rows gemm1 (also reversed) wrote last... gemm1 reversed writes rows
    // 0..127 last, and gemm2 reversed starts at the END. To chain correctly, gemm2
    // must start where gemm1 FINISHED: gemm1 (REV=1) finishes at low row indices, so
    // gemm2 must run ASCENDING? No: gemm1 REV=1 processes by=1599 first, by=0 last ->
    // h1 rows [0,128) written last -> gemm2 should start at by=0 -> REV=0... but then
    // gemm2 ascending reads match gemm1's descending writes only at the boundary.
    // Correct pairing: gemm1 REV=1 (chains to prep ascending), gemm2 REV=0 (chains to
    // gemm1 descending). Math is order-invariant either way.
    hgemm_kernel<128, 128, 128, 64, 64, 2, 2, 3, 1>
        <<<dim3((HDIM / 2) / 128, M_ROWS / 128), 128, SMEM_BN128>>>(h1, W2t, db2, (void*)dep,
                                                                    dW3, HDIM / 2, HDIM);

    // join: bones needs both depth (main) and F1 (side)
    cudaStreamWaitEvent(0, evF1, 0);
    bones_kernel<<<BATCH / NB, 512, SMEM_BONES>>>(poses2d, confid, dep, F1, cW1, cW2, cb2, cW3,
                                                  cb3, out);
}